// round 11
// baseline (speedup 1.0000x reference)
#include <cuda_runtime.h>
#include <cuda_bf16.h>
#include <cstdint>

// Fused soft-VQ, tf32 mma.sync, transposed operands + cp.async 2-stage C ring
// with in-place RNA tf32 conversion of each landed stage.
//   MMA1: S^T[32j x 16r/warp] = C * X^T
//   MMA2: O^T[32d/warp x 128r] = C^T * P^T
// out = softmax(-10 * ||x - C||) @ C ; N=32768, K=8192, D=256

#define DD  256
#define BM  128
#define BN  32
#define XS_STRIDE 260   // 65 quads (odd) -> ldmatrix conflict-free
#define CS_STRIDE 260
#define PS_STRIDE 36    // 9 quads (odd)
#define CS_STAGE  (BN * CS_STRIDE)                  // 8320 floats / stage

#define NMAX 32768
#define KMAX 8192

// smem float offsets
#define OFF_XS 0
#define OFF_CS (OFF_XS + BM * XS_STRIDE)            // 33280
#define OFF_PS (OFF_CS + 2 * CS_STAGE)              // 49920
#define OFF_LB (OFF_PS + BM * PS_STRIDE)            // 54528
#define SMEM_FLOATS (OFF_LB + BM)                   // 54656
#define SMEM_BYTES (SMEM_FLOATS * 4)                // 218624

#define LOG2E10 14.4269504088896f   // 10 * log2(e)

__device__ float g_x2[NMAX];
__device__ float g_c2[KMAX];

// ---------------- helpers ----------------
__device__ __forceinline__ uint32_t cvt_rna_tf32(float v) {
    uint32_t u;
    asm("cvt.rna.tf32.f32 %0, %1;" : "=r"(u) : "f"(v));
    return u;
}
__device__ __forceinline__ float sqrt_approx(float v) {
    float r;
    asm("sqrt.approx.f32 %0, %1;" : "=f"(r) : "f"(v));
    return r;
}
__device__ __forceinline__ float ex2_approx(float v) {
    float r;
    asm("ex2.approx.f32 %0, %1;" : "=f"(r) : "f"(v));
    return r;
}
__device__ __forceinline__ void ldm_x4(uint32_t addr, uint32_t& r0, uint32_t& r1,
                                       uint32_t& r2, uint32_t& r3) {
    asm volatile("ldmatrix.sync.aligned.m8n8.x4.shared.b16 {%0,%1,%2,%3}, [%4];"
                 : "=r"(r0), "=r"(r1), "=r"(r2), "=r"(r3) : "r"(addr));
}
__device__ __forceinline__ void mma_tf32(float* d, const uint32_t* a,
                                         uint32_t b0, uint32_t b1) {
    asm volatile(
        "mma.sync.aligned.m16n8k8.row.col.f32.tf32.tf32.f32 "
        "{%0,%1,%2,%3}, {%4,%5,%6,%7}, {%8,%9}, {%0,%1,%2,%3};"
        : "+f"(d[0]), "+f"(d[1]), "+f"(d[2]), "+f"(d[3])
        : "r"(a[0]), "r"(a[1]), "r"(a[2]), "r"(a[3]), "r"(b0), "r"(b1));
}
__device__ __forceinline__ void cp16(uint32_t dst, const float* src) {
    asm volatile("cp.async.cg.shared.global [%0], [%1], 16;"
                 :: "r"(dst), "l"(src));
}
__device__ __forceinline__ void cp_commit() {
    asm volatile("cp.async.commit_group;");
}
__device__ __forceinline__ void cp_wait1() {
    asm volatile("cp.async.wait_group 1;");
}

// ---------------- prep: row norms of x and C ----------------
__global__ void prep_norms(const float* __restrict__ x,
                           const float* __restrict__ cbk, int N, int K) {
    int w    = (blockIdx.x * blockDim.x + threadIdx.x) >> 5;
    int lane = threadIdx.x & 31;
    if (w >= N + K) return;
    const float* src;
    float* dst;
    if (w < N) { src = x + (long long)w * DD;         dst = g_x2 + w; }
    else       { src = cbk + (long long)(w - N) * DD; dst = g_c2 + (w - N); }
    float s = 0.f;
    #pragma unroll
    for (int i = lane; i < DD / 4; i += 32) {
        float4 v = ((const float4*)src)[i];
        s += v.x * v.x + v.y * v.y + v.z * v.z + v.w * v.w;
    }
    #pragma unroll
    for (int d = 16; d > 0; d >>= 1) s += __shfl_xor_sync(0xffffffffu, s, d);
    if (lane == 0) *dst = s;
}

// ---------------- main fused kernel ----------------
__global__ __launch_bounds__(256, 1)
void vq_tc_kernel(const float* __restrict__ x,
                  const float* __restrict__ cbk,
                  float* __restrict__ out, int Ktot)
{
    extern __shared__ float sm[];
    float* xs = sm + OFF_XS;
    float* cs = sm + OFF_CS;   // 2 stages
    float* ps = sm + OFF_PS;
    float* lb = sm + OFF_LB;

    const int tid  = threadIdx.x;
    const int w    = tid >> 5;      // 0..7 : r-stripe 16w (MMA1), d-range 32w (MMA2)
    const int lane = tid & 31;
    const int q    = lane >> 2;     // 0..7
    const int m    = lane & 3;      // 0..3
    const int lrow = lane & 15;
    const int lkof = (lane & 16) >> 2;
    const long long row0 = (long long)blockIdx.x * BM;

    const uint32_t xs_b = (uint32_t)__cvta_generic_to_shared(xs);
    const uint32_t cs_b = (uint32_t)__cvta_generic_to_shared(cs);
    const uint32_t ps_b = (uint32_t)__cvta_generic_to_shared(ps);

    // ---- stage x tile [128][256] (cvt.rna -> tf32 bits) ----
    for (int e = tid; e < BM * DD / 4; e += 256) {
        int r = e >> 6, c4 = e & 63;
        float4 v = ((const float4*)(x + (row0 + r) * DD))[c4];
        uint4 u;
        u.x = cvt_rna_tf32(v.x); u.y = cvt_rna_tf32(v.y);
        u.z = cvt_rna_tf32(v.z); u.w = cvt_rna_tf32(v.w);
        *(uint4*)(xs + r * XS_STRIDE + c4 * 4) = u;
    }

    // ---- per-lane r constants (warp r-stripe: 16w .. 16w+15) ----
    float x2v[2][2], m2v[2][2];
    #pragma unroll
    for (int nf = 0; nf < 2; nf++)
        #pragma unroll
        for (int par = 0; par < 2; par++) {
            int r = 16 * w + 8 * nf + 2 * m + par;
            float xx = g_x2[row0 + r];
            x2v[nf][par] = xx;
            m2v[nf][par] = LOG2E10 * sqrt_approx(xx);
        }

    // O^T accumulators: d-range 32w..+31 (2 mtd), all 128 r (16 nt)
    float o[2][16][4];
    #pragma unroll
    for (int mtd = 0; mtd < 2; mtd++)
        #pragma unroll
        for (int nt = 0; nt < 16; nt++)
            #pragma unroll
            for (int c = 0; c < 4; c++) o[mtd][nt][c] = 0.f;
    float lsum[2][2] = {{0.f, 0.f}, {0.f, 0.f}};

    const int nTiles = Ktot / BN;

    // ---- prologue: issue C-tile stages 0 and 1 ----
    #pragma unroll
    for (int s = 0; s < 2; s++) {
        const float* src0 = cbk + (long long)s * BN * DD;
        #pragma unroll
        for (int e = tid; e < BN * DD / 4; e += 256) {
            int r = e >> 6, c4 = e & 63;
            cp16(cs_b + (s * CS_STAGE + r * CS_STRIDE + c4 * 4) * 4,
                 src0 + r * DD + c4 * 4);
        }
        cp_commit();
    }

    for (int kt = 0; kt < nTiles; kt++) {
        const int col0 = kt * BN;
        const int buf  = kt & 1;
        float*  csb   = cs + buf * CS_STAGE;
        const uint32_t cs_bb = cs_b + buf * CS_STAGE * 4;

        // c2 for this lane's j positions (j = 16mt + q + 8h)
        float c2v[2][2];
        #pragma unroll
        for (int mt = 0; mt < 2; mt++)
            #pragma unroll
            for (int h = 0; h < 2; h++)
                c2v[mt][h] = g_c2[col0 + 16 * mt + q + 8 * h];

        cp_wait1();          // stage kt landed
        __syncthreads();     // all warps see it (also: ps reads of kt-1 done)

        // ---- in-place RNA convert of the landed stage (fp32 -> tf32 bits) ----
        #pragma unroll
        for (int e = tid; e < BN * DD / 4; e += 256) {
            int r = e >> 6, c4 = e & 63;
            float* p4 = csb + r * CS_STRIDE + c4 * 4;
            float4 v = *(const float4*)p4;
            uint4 u;
            u.x = cvt_rna_tf32(v.x); u.y = cvt_rna_tf32(v.y);
            u.z = cvt_rna_tf32(v.z); u.w = cvt_rna_tf32(v.w);
            *(uint4*)p4 = u;
        }
        __syncthreads();

        // ---- MMA1: S^T[32j x 16r] = C * X^T ----
        float sfr[2][2][4];
        #pragma unroll
        for (int mt = 0; mt < 2; mt++)
            #pragma unroll
            for (int nf = 0; nf < 2; nf++)
                #pragma unroll
                for (int c = 0; c < 4; c++) sfr[mt][nf][c] = 0.f;

        #pragma unroll 8
        for (int kk = 0; kk < 32; kk++) {
            const int k0 = kk * 8;
            uint32_t a[2][4];
            #pragma unroll
            for (int mt = 0; mt < 2; mt++) {
                uint32_t ad = cs_bb +
                    ((16 * mt + lrow) * CS_STRIDE + k0 + lkof) * 4;
                ldm_x4(ad, a[mt][0], a[mt][1], a[mt][2], a[mt][3]);
            }
            uint32_t r0, r1, r2, r3;
            {
                uint32_t ad = xs_b +
                    ((16 * w + lrow) * XS_STRIDE + k0 + lkof) * 4;
                ldm_x4(ad, r0, r1, r2, r3);
            }
            #pragma unroll
            for (int mt = 0; mt < 2; mt++) {
                mma_tf32(sfr[mt][0], a[mt], r0, r2);
                mma_tf32(sfr[mt][1], a[mt], r1, r3);
            }
        }

        // ---- epilogue: p = exp2(m2[r] - L*sqrt(x2[r]+c2[j]-2s)) ----
        #pragma unroll
        for (int mt = 0; mt < 2; mt++)
            #pragma unroll
            for (int nf = 0; nf < 2; nf++) {
                float s0 = sfr[mt][nf][0];   // (j0+q,   rA)
                float s1 = sfr[mt][nf][1];   // (j0+q,   rA+1)
                float s2 = sfr[mt][nf][2];   // (j0+q+8, rA)
                float s3 = sfr[mt][nf][3];   // (j0+q+8, rA+1)
                float sq0 = fmaf(-2.f, s0, x2v[nf][0]) + c2v[mt][0];
                float sq1 = fmaf(-2.f, s1, x2v[nf][1]) + c2v[mt][0];
                float sq2 = fmaf(-2.f, s2, x2v[nf][0]) + c2v[mt][1];
                float sq3 = fmaf(-2.f, s3, x2v[nf][1]) + c2v[mt][1];
                float r0 = sqrt_approx(fmaxf(sq0, 0.f));
                float r1 = sqrt_approx(fmaxf(sq1, 0.f));
                float r2 = sqrt_approx(fmaxf(sq2, 0.f));
                float r3 = sqrt_approx(fmaxf(sq3, 0.f));
                float p0 = ex2_approx(fmaf(-LOG2E10, r0, m2v[nf][0]));
                float p1 = ex2_approx(fmaf(-LOG2E10, r1, m2v[nf][1]));
                float p2 = ex2_approx(fmaf(-LOG2E10, r2, m2v[nf][0]));
                float p3 = ex2_approx(fmaf(-LOG2E10, r3, m2v[nf][1]));
                lsum[nf][0] += p0 + p2;
                lsum[nf][1] += p1 + p3;
                sfr[mt][nf][0] = __uint_as_float(cvt_rna_tf32(p0));
                sfr[mt][nf][1] = __uint_as_float(cvt_rna_tf32(p1));
                sfr[mt][nf][2] = __uint_as_float(cvt_rna_tf32(p2));
                sfr[mt][nf][3] = __uint_as_float(cvt_rna_tf32(p3));
            }

        // ---- store P (row-major [r][j]) — conflict-free scatter ----
        #pragma unroll
        for (int mt = 0; mt < 2; mt++)
            #pragma unroll
            for (int nf = 0; nf < 2; nf++) {
                int jl = 16 * mt + q;
                int rA = 16 * w + 8 * nf + 2 * m;
                ps[rA * PS_STRIDE + jl]           = sfr[mt][nf][0];
                ps[(rA + 1) * PS_STRIDE + jl]     = sfr[mt][nf][1];
                ps[rA * PS_STRIDE + jl + 8]       = sfr[mt][nf][2];
                ps[(rA + 1) * PS_STRIDE + jl + 8] = sfr[mt][nf][3];
            }
        __syncthreads();

        // ---- MMA2: O^T += C^T * P^T ----
        #pragma unroll
        for (int jk = 0; jk < 4; jk++) {
            const int jg = 8 * jk;
            uint32_t a2[2][4];
            #pragma unroll
            for (int mtd = 0; mtd < 2; mtd++) {
                const float* cp0 = csb + (jg + m) * CS_STRIDE + 32 * w + 16 * mtd;
                const float* cp1 = csb + (jg + 4 + m) * CS_STRIDE + 32 * w + 16 * mtd;
                a2[mtd][0] = __float_as_uint(cp0[q]);
                a2[mtd][1] = __float_as_uint(cp0[q + 8]);
                a2[mtd][2] = __float_as_uint(cp1[q]);
                a2[mtd][3] = __float_as_uint(cp1[q + 8]);
            }
            uint32_t bb[16][2];
            #pragma unroll
            for (int g = 0; g < 8; g++) {
                uint32_t r0, r1, r2, r3;
                uint32_t ad = ps_b +
                    ((16 * g + lrow) * PS_STRIDE + jg + lkof) * 4;
                ldm_x4(ad, r0, r1, r2, r3);
                bb[2 * g][0] = r0;     bb[2 * g][1] = r2;
                bb[2 * g + 1][0] = r1; bb[2 * g + 1][1] = r3;
            }
            #pragma unroll
            for (int mtd = 0; mtd < 2; mtd++)
                #pragma unroll
                for (int nt = 0; nt < 16; nt++)
                    mma_tf32(o[mtd][nt], a2[mtd], bb[nt][0], bb[nt][1]);
        }
        __syncthreads();   // buffer `buf` fully consumed

        // ---- issue C-tile kt+2 into the freed stage ----
        if (kt + 2 < nTiles) {
            const float* src0 = cbk + (long long)(col0 + 2 * BN) * DD;
            #pragma unroll
            for (int e = tid; e < BN * DD / 4; e += 256) {
                int r = e >> 6, c4 = e & 63;
                cp16(cs_b + (buf * CS_STAGE + r * CS_STRIDE + c4 * 4) * 4,
                     src0 + r * DD + c4 * 4);
            }
        }
        cp_commit();   // keep group counting aligned even on tail tiles
    }

    // ---- reduce lsum over q-lanes (j direction), publish lb[r] ----
    #pragma unroll
    for (int nf = 0; nf < 2; nf++)
        #pragma unroll
        for (int par = 0; par < 2; par++) {
            float v = lsum[nf][par];
            v += __shfl_xor_sync(0xffffffffu, v, 4);
            v += __shfl_xor_sync(0xffffffffu, v, 8);
            v += __shfl_xor_sync(0xffffffffu, v, 16);
            if (q == 0)
                lb[16 * w + 8 * nf + 2 * m + par] = v;
        }
    __syncthreads();

    // ---- finalize: out[r][d] = O^T[d][r] / l[r] ----
    #pragma unroll
    for (int nt = 0; nt < 16; nt++) {
        int rA = 8 * nt + 2 * m;
        float invA = 1.f / lb[rA];
        float invB = 1.f / lb[rA + 1];
        #pragma unroll
        for (int mtd = 0; mtd < 2; mtd++) {
            int d0 = 32 * w + 16 * mtd;
            float* oA = out + (row0 + rA) * DD + d0;
            float* oB = out + (row0 + rA + 1) * DD + d0;
            oA[q]     = o[mtd][nt][0] * invA;
            oB[q]     = o[mtd][nt][1] * invB;
            oA[q + 8] = o[mtd][nt][2] * invA;
            oB[q + 8] = o[mtd][nt][3] * invB;
        }
    }
}

// Fill possible tail of d_out (the reference's second tuple element, -1)
__global__ void fill_tail_kernel(float* p, long long n)
{
    long long i = (long long)blockIdx.x * blockDim.x + threadIdx.x;
    if (i < n) p[i] = -1.0f;
}

extern "C" void kernel_launch(void* const* d_in, const int* in_sizes, int n_in,
                              void* d_out, int out_size)
{
    const float* x   = (const float*)d_in[0];
    const float* cbk = (const float*)d_in[1];
    float* out = (float*)d_out;

    const int N = in_sizes[0] / DD;   // 32768
    const int K = in_sizes[1] / DD;   // 8192

    // prep: row norms
    {
        int warps = N + K;
        int thr = 256;
        int blocks = (warps * 32 + thr - 1) / thr;
        prep_norms<<<blocks, thr>>>(x, cbk, N, K);
    }

    cudaFuncSetAttribute(vq_tc_kernel,
                         cudaFuncAttributeMaxDynamicSharedMemorySize, SMEM_BYTES);
    vq_tc_kernel<<<N / BM, 256, SMEM_BYTES>>>(x, cbk, out, K);

    long long nd = (long long)N * DD;
    if ((long long)out_size > nd) {
        long long tail = (long long)out_size - nd;
        int thr = 256;
        int blocks = (int)((tail + thr - 1) / thr);
        fill_tail_kernel<<<blocks, thr>>>(out + nd, tail);
    }
}